// round 7
// baseline (speedup 1.0000x reference)
#include <cuda_runtime.h>
#include <cuda_bf16.h>
#include <cstdint>

// ---------------------------------------------------------------------------
// SpatialLocalAwareAttention — occupancy round: lean attn + split local merge
// B=2, T=4, H=W=32, D=256, heads=8, dh=32, local 3x3
// ---------------------------------------------------------------------------

#define D_MODEL 256
#define N_HEADS 8
#define DHEAD   32
#define BTDIM   8
#define NTOK    1024
#define NROWS   (BTDIM * NTOK)   // 8192
#define IMG     32

typedef unsigned long long u64;

// ---------------- f32x2 helpers ----------------
__device__ __forceinline__ u64 pack2(float lo, float hi) {
    u64 r; asm("mov.b64 %0, {%1, %2};" : "=l"(r) : "f"(lo), "f"(hi)); return r;
}
__device__ __forceinline__ float2 unpack2(u64 v) {
    float2 r; asm("mov.b64 {%0, %1}, %2;" : "=f"(r.x), "=f"(r.y) : "l"(v)); return r;
}
__device__ __forceinline__ void ffma2(u64& acc, u64 a, u64 b) {
    asm("fma.rn.f32x2 %0, %1, %2, %0;" : "+l"(acc) : "l"(a), "l"(b));
}

// ---------------- mma / misc helpers ----------------
__device__ __forceinline__ void mma_bf16(float* c, const uint32_t* a,
                                         const uint32_t* b)
{
    asm volatile(
        "mma.sync.aligned.m16n8k16.row.col.f32.bf16.bf16.f32 "
        "{%0,%1,%2,%3}, {%4,%5,%6,%7}, {%8,%9}, {%0,%1,%2,%3};"
        : "+f"(c[0]), "+f"(c[1]), "+f"(c[2]), "+f"(c[3])
        : "r"(a[0]), "r"(a[1]), "r"(a[2]), "r"(a[3]),
          "r"(b[0]), "r"(b[1]));
}
__device__ __forceinline__ uint32_t cvt_bf16x2(float hi, float lo) {
    uint32_t r;
    asm("cvt.rn.bf16x2.f32 %0, %1, %2;" : "=r"(r) : "f"(hi), "f"(lo));
    return r;
}
__device__ __forceinline__ float ex2f(float x) {
    float r; asm("ex2.approx.f32 %0, %1;" : "=f"(r) : "f"(x)); return r;
}
__device__ __forceinline__ uint32_t smem_u32(const void* p) {
    uint32_t a;
    asm("{ .reg .u64 t; cvta.to.shared.u64 t, %1; cvt.u32.u64 %0, t; }"
        : "=r"(a) : "l"(p));
    return a;
}
__device__ __forceinline__ void cp_async16(uint32_t dst, const void* src) {
    asm volatile("cp.async.cg.shared.global [%0], [%1], 16;"
                 :: "r"(dst), "l"(__cvta_generic_to_global(src)) : "memory");
}
#define CP_COMMIT() asm volatile("cp.async.commit_group;" ::: "memory")
#define CP_WAIT(n)  asm volatile("cp.async.wait_group %0;" :: "n"(n) : "memory")

// scale folded into Q: softmax computed in exp2 domain (exact base change)
#define QSCALE (0.17677669529663687f * 1.4426950408889634f)

// ---------------- global scratch ----------------
__device__ __align__(16) __nv_bfloat16 g_xnh [NROWS * D_MODEL];
__device__ __align__(16) __nv_bfloat16 g_xnl [NROWS * D_MODEL];
__device__ __align__(16) __nv_bfloat16 g_ctxh[NROWS * D_MODEL];
__device__ __align__(16) __nv_bfloat16 g_ctxl[NROWS * D_MODEL];
__device__ __align__(16) __nv_bfloat16 g_wh  [6 * D_MODEL * D_MODEL];
__device__ __align__(16) __nv_bfloat16 g_wl  [6 * D_MODEL * D_MODEL];

__device__ float g_q  [NROWS * D_MODEL];                 // fp32 q (+bias)
__device__ float g_kl [NROWS * D_MODEL];                 // fp32 local k
__device__ float g_vl [NROWS * D_MODEL];                 // fp32 local v
__device__ __align__(16) __nv_bfloat16 g_kbh[NROWS * D_MODEL];
__device__ __align__(16) __nv_bfloat16 g_kbl[NROWS * D_MODEL];
__device__ __align__(16) __nv_bfloat16 g_vth[NROWS * D_MODEL];   // v transposed
__device__ __align__(16) __nv_bfloat16 g_vtl[NROWS * D_MODEL];

__device__ __align__(16) float g_oacc[NROWS * D_MODEL];  // unnormalized O [bh][n][32]
__device__ float g_om[NROWS * N_HEADS / N_HEADS * N_HEADS]; // [bh*1024+n] -> 65536
__device__ float g_ol[65536];

// ---------------------------------------------------------------------------
// Kernel 0: weights -> bf16 hi/lo
// ---------------------------------------------------------------------------
__global__ __launch_bounds__(256) void wprep_kernel(const float* __restrict__ Wq,
                                                    const float* __restrict__ Wk,
                                                    const float* __restrict__ Wv,
                                                    const float* __restrict__ Wkl,
                                                    const float* __restrict__ Wvl,
                                                    const float* __restrict__ Wo)
{
    int idx = blockIdx.x * 256 + threadIdx.x;
    int z = idx >> 16;
    const float* Ws;
    switch (z) {
        case 0: Ws = Wq;  break;
        case 1: Ws = Wk;  break;
        case 2: Ws = Wv;  break;
        case 3: Ws = Wkl; break;
        case 4: Ws = Wvl; break;
        default: Ws = Wo; break;
    }
    float a = Ws[idx & 65535];
    __nv_bfloat16 hi = __float2bfloat16(a);
    g_wh[idx] = hi;
    g_wl[idx] = __float2bfloat16(a - __bfloat162float(hi));
}

// ---------------------------------------------------------------------------
// Kernel 1: layernorm + gather; emits bf16 hi/lo of xn
// ---------------------------------------------------------------------------
__global__ __launch_bounds__(256) void ln_kernel(const float* __restrict__ x,
                                                 const float* __restrict__ gamma,
                                                 const float* __restrict__ beta)
{
    int row = blockIdx.x;
    int d   = threadIdx.x;
    int bt  = row >> 10;
    int n   = row & 1023;
    int b   = bt >> 2;
    int t   = bt & 3;

    float v = x[((size_t)(b * D_MODEL + d) * 4 + t) * 1024 + n];

    float s  = v;
    float s2 = v * v;
    #pragma unroll
    for (int off = 16; off > 0; off >>= 1) {
        s  += __shfl_down_sync(0xffffffffu, s,  off);
        s2 += __shfl_down_sync(0xffffffffu, s2, off);
    }
    __shared__ float ws[8], ws2[8];
    __shared__ float mu_s, rstd_s;
    int lane = d & 31, wid = d >> 5;
    if (lane == 0) { ws[wid] = s; ws2[wid] = s2; }
    __syncthreads();
    if (d == 0) {
        float a = 0.f, b2 = 0.f;
        #pragma unroll
        for (int w = 0; w < 8; w++) { a += ws[w]; b2 += ws2[w]; }
        float mu  = a * (1.0f / 256.0f);
        float var = b2 * (1.0f / 256.0f) - mu * mu;
        mu_s   = mu;
        rstd_s = rsqrtf(var + 1e-6f);
    }
    __syncthreads();
    float xnv = (v - mu_s) * rstd_s * gamma[d] + beta[d];
    __nv_bfloat16 hi = __float2bfloat16(xnv);
    g_xnh[(size_t)row * 256 + d] = hi;
    g_xnl[(size_t)row * 256 + d] = __float2bfloat16(xnv - __bfloat162float(hi));
}

// ---------------------------------------------------------------------------
// Kernel 2/4: bf16x3 mma.sync GEMM (validated), per-z epilogues.
// ---------------------------------------------------------------------------
#define ASTR 72
#define GEMM_SMEM_BYTES (4 * 128 * ASTR * 2)   // 73728

__global__ __launch_bounds__(256) void gemm_mma_kernel(const float* __restrict__ qb,
                                                       float* __restrict__ out,
                                                       int z_base)
{
    extern __shared__ __nv_bfloat16 smem[];
    __nv_bfloat16* sAh = smem;
    __nv_bfloat16* sAl = smem + 128 * ASTR;
    __nv_bfloat16* sBh = smem + 2 * 128 * ASTR;
    __nv_bfloat16* sBl = smem + 3 * 128 * ASTR;

    const int tid  = threadIdx.x;
    const int wid  = tid >> 5;
    const int lane = tid & 31;
    const int z    = blockIdx.z + z_base;
    const int m0   = blockIdx.y * 128;
    const int cg0  = blockIdx.x * 128;

    const __nv_bfloat16* Ah = (z < 5) ? g_xnh : g_ctxh;
    const __nv_bfloat16* Al = (z < 5) ? g_xnl : g_ctxl;
    const __nv_bfloat16* Bh = g_wh + (size_t)z * 65536;
    const __nv_bfloat16* Bl = g_wl + (size_t)z * 65536;

    const int wm = (wid >> 2) * 64;
    const int wn = (wid & 3) * 32;
    const int g   = lane >> 2;
    const int tig = lane & 3;

    float acc[4][4][4];
    #pragma unroll
    for (int i = 0; i < 4; i++)
        #pragma unroll
        for (int j = 0; j < 4; j++)
            #pragma unroll
            for (int e = 0; e < 4; e++) acc[i][j][e] = 0.f;

    const int lrow = tid >> 1;
    const int lhalf = (tid & 1) * 32;

    for (int k0 = 0; k0 < 256; k0 += 64) {
        __syncthreads();
        {
            const uint4* gah = (const uint4*)(Ah + (size_t)(m0 + lrow) * 256 + k0 + lhalf);
            const uint4* gal = (const uint4*)(Al + (size_t)(m0 + lrow) * 256 + k0 + lhalf);
            const uint4* gbh = (const uint4*)(Bh + (size_t)(cg0 + lrow) * 256 + k0 + lhalf);
            const uint4* gbl = (const uint4*)(Bl + (size_t)(cg0 + lrow) * 256 + k0 + lhalf);
            uint4* dah = (uint4*)(sAh + lrow * ASTR + lhalf);
            uint4* dal = (uint4*)(sAl + lrow * ASTR + lhalf);
            uint4* dbh = (uint4*)(sBh + lrow * ASTR + lhalf);
            uint4* dbl = (uint4*)(sBl + lrow * ASTR + lhalf);
            #pragma unroll
            for (int q = 0; q < 4; q++) {
                dah[q] = gah[q];
                dal[q] = gal[q];
                dbh[q] = gbh[q];
                dbl[q] = gbl[q];
            }
        }
        __syncthreads();

        #pragma unroll
        for (int ks = 0; ks < 4; ks++) {
            const int koff = ks * 16;
            uint32_t ah[4][4], al[4][4];
            #pragma unroll
            for (int i = 0; i < 4; i++) {
                const int r0 = wm + i * 16 + g;
                const __nv_bfloat16* ph0 = sAh + r0 * ASTR + koff + tig * 2;
                const __nv_bfloat16* ph1 = ph0 + 8 * ASTR;
                const __nv_bfloat16* pl0 = sAl + r0 * ASTR + koff + tig * 2;
                const __nv_bfloat16* pl1 = pl0 + 8 * ASTR;
                ah[i][0] = *(const uint32_t*)(ph0);
                ah[i][1] = *(const uint32_t*)(ph1);
                ah[i][2] = *(const uint32_t*)(ph0 + 8);
                ah[i][3] = *(const uint32_t*)(ph1 + 8);
                al[i][0] = *(const uint32_t*)(pl0);
                al[i][1] = *(const uint32_t*)(pl1);
                al[i][2] = *(const uint32_t*)(pl0 + 8);
                al[i][3] = *(const uint32_t*)(pl1 + 8);
            }
            #pragma unroll
            for (int j = 0; j < 4; j++) {
                const int nb = wn + j * 8 + g;
                const __nv_bfloat16* pb = sBh + nb * ASTR + koff + tig * 2;
                const __nv_bfloat16* pc = sBl + nb * ASTR + koff + tig * 2;
                uint32_t bh[2], bl[2];
                bh[0] = *(const uint32_t*)(pb);
                bh[1] = *(const uint32_t*)(pb + 8);
                bl[0] = *(const uint32_t*)(pc);
                bl[1] = *(const uint32_t*)(pc + 8);
                #pragma unroll
                for (int i = 0; i < 4; i++) {
                    mma_bf16(acc[i][j], ah[i], bh);
                    mma_bf16(acc[i][j], ah[i], bl);
                    mma_bf16(acc[i][j], al[i], bh);
                }
            }
        }
    }

    // ---- epilogue ----
    if (z == 5) {
        #pragma unroll
        for (int i = 0; i < 4; i++) {
            const int mlo = m0 + wm + i * 16 + g;
            const int mhi = mlo + 8;
            const int bt_ = mlo >> 10;
            const int b   = bt_ >> 2;
            const int t   = bt_ & 3;
            const int nlo = mlo & 1023;
            const int nhi = mhi & 1023;
            #pragma unroll
            for (int j = 0; j < 4; j++) {
                const int cc = cg0 + wn + j * 8 + tig * 2;
                out[((size_t)((b * D_MODEL + cc)     * 4 + t)) * 1024 + nlo] = acc[i][j][0];
                out[((size_t)((b * D_MODEL + cc + 1) * 4 + t)) * 1024 + nlo] = acc[i][j][1];
                out[((size_t)((b * D_MODEL + cc)     * 4 + t)) * 1024 + nhi] = acc[i][j][2];
                out[((size_t)((b * D_MODEL + cc + 1) * 4 + t)) * 1024 + nhi] = acc[i][j][3];
            }
        }
        return;
    }

    #pragma unroll
    for (int i = 0; i < 4; i++) {
        const int mlo = m0 + wm + i * 16 + g;
        const int mhi = mlo + 8;
        const int bt_ = mlo >> 10;
        const int nlo = mlo & 1023;
        const int nhi = mhi & 1023;
        #pragma unroll
        for (int j = 0; j < 4; j++) {
            const int cc   = cg0 + wn + j * 8 + tig * 2;
            const int head = cc >> 5;
            const int dh0  = cc & 31;
            const int bh2  = bt_ * N_HEADS + head;

            if (z == 0) {
                float b0 = qb[cc], b1 = qb[cc + 1];
                float* base = g_q + ((size_t)bh2 * NTOK) * DHEAD + dh0;
                *(float2*)(base + (size_t)nlo * DHEAD) =
                    make_float2(acc[i][j][0] + b0, acc[i][j][1] + b1);
                *(float2*)(base + (size_t)nhi * DHEAD) =
                    make_float2(acc[i][j][2] + b0, acc[i][j][3] + b1);
            } else if (z == 1) {
                size_t base = ((size_t)bh2 * NTOK) * DHEAD + dh0;
                #pragma unroll
                for (int half = 0; half < 2; half++) {
                    const int nn = half ? nhi : nlo;
                    float v0 = acc[i][j][half * 2];
                    float v1 = acc[i][j][half * 2 + 1];
                    __nv_bfloat16 h0 = __float2bfloat16(v0);
                    __nv_bfloat16 h1 = __float2bfloat16(v1);
                    *(__nv_bfloat162*)(g_kbh + base + (size_t)nn * DHEAD) =
                        __halves2bfloat162(h0, h1);
                    *(__nv_bfloat162*)(g_kbl + base + (size_t)nn * DHEAD) =
                        __halves2bfloat162(
                            __float2bfloat16(v0 - __bfloat162float(h0)),
                            __float2bfloat16(v1 - __bfloat162float(h1)));
                }
            } else if (z == 2) {
                #pragma unroll
                for (int half = 0; half < 2; half++) {
                    const int nn = half ? nhi : nlo;
                    float v0 = acc[i][j][half * 2];
                    float v1 = acc[i][j][half * 2 + 1];
                    __nv_bfloat16 h0 = __float2bfloat16(v0);
                    __nv_bfloat16 h1 = __float2bfloat16(v1);
                    size_t i0 = ((size_t)bh2 * DHEAD + dh0) * NTOK + nn;
                    size_t i1 = ((size_t)bh2 * DHEAD + dh0 + 1) * NTOK + nn;
                    g_vth[i0] = h0;
                    g_vth[i1] = h1;
                    g_vtl[i0] = __float2bfloat16(v0 - __bfloat162float(h0));
                    g_vtl[i1] = __float2bfloat16(v1 - __bfloat162float(h1));
                }
            } else {
                float* dst = (z == 3) ? g_kl : g_vl;
                float* base = dst + ((size_t)bh2 * NTOK) * DHEAD + dh0;
                *(float2*)(base + (size_t)nlo * DHEAD) =
                    make_float2(acc[i][j][0], acc[i][j][1]);
                *(float2*)(base + (size_t)nhi * DHEAD) =
                    make_float2(acc[i][j][2], acc[i][j][3]);
            }
        }
    }
}

// ---------------------------------------------------------------------------
// Kernel 3: flash attention mainloop only. Q in regs, cp.async ping-pong,
// exp2-domain softmax, writes unnormalized O + (m,l) to global scratch.
// ---------------------------------------------------------------------------
#define QS 40
#define VS 72
#define BUF_KH   0
#define BUF_KL   (64 * QS * 2)
#define BUF_VH   (2 * 64 * QS * 2)
#define BUF_VL   (BUF_VH + 32 * VS * 2)
#define BUF_BYTES (BUF_VL + 32 * VS * 2)       // 19456
#define ATTN_SMEM_BYTES (2 * BUF_BYTES)        // 38912

__global__ __launch_bounds__(256, 3) void attn_mma_kernel()
{
    extern __shared__ char sm_raw[];

    const int tid  = threadIdx.x;
    const int wid  = tid >> 5;
    const int lane = tid & 31;
    const int g    = lane >> 2;
    const int tig  = lane & 3;
    const int bh   = blockIdx.z * N_HEADS + blockIdx.y;
    const int n0   = blockIdx.x * 128;

    const int row = wid * 16 + g;

    // ---- Q fragments in registers (scaled by QSCALE, hi/lo split) ----
    uint32_t qfh[2][4], qfl[2][4];
    {
        const float* qbase = g_q + ((size_t)bh * NTOK + n0) * DHEAD;
        #pragma unroll
        for (int s = 0; s < 2; s++) {
            const int ko = s * 16 + tig * 2;
            #pragma unroll
            for (int e = 0; e < 4; e++) {
                const int rr  = row + (e & 1) * 8;
                const int col = ko + (e >> 1) * 8;
                float2 v = *(const float2*)(qbase + (size_t)rr * DHEAD + col);
                v.x *= QSCALE; v.y *= QSCALE;
                __nv_bfloat16 h0 = __float2bfloat16(v.x);
                __nv_bfloat16 h1 = __float2bfloat16(v.y);
                qfh[s][e] = cvt_bf16x2(v.y, v.x);
                qfl[s][e] = cvt_bf16x2(v.y - __bfloat162float(h1),
                                       v.x - __bfloat162float(h0));
            }
        }
    }

    // ---- per-thread cp.async slots ----
    const int key = tid >> 2, dofk = (tid & 3) * 8;
    const int vd  = tid >> 3, kofv = (tid & 7) * 8;
    const size_t kbase_idx = ((size_t)bh * NTOK + key) * DHEAD + dofk;
    const size_t vbase_idx = ((size_t)bh * DHEAD + vd) * NTOK + kofv;
    const uint32_t sm_base = smem_u32(sm_raw);
    const uint32_t kh_dst = sm_base + BUF_KH + (key * QS + dofk) * 2;
    const uint32_t kl_dst = sm_base + BUF_KL + (key * QS + dofk) * 2;
    const uint32_t vh_dst = sm_base + BUF_VH + (vd * VS + kofv) * 2;
    const uint32_t vl_dst = sm_base + BUF_VL + (vd * VS + kofv) * 2;

    #define PREFETCH(t0_, bofs_) do {                                   \
        cp_async16(kh_dst + (bofs_), g_kbh + kbase_idx + (size_t)(t0_) * DHEAD); \
        cp_async16(kl_dst + (bofs_), g_kbl + kbase_idx + (size_t)(t0_) * DHEAD); \
        cp_async16(vh_dst + (bofs_), g_vth + vbase_idx + (t0_));        \
        cp_async16(vl_dst + (bofs_), g_vtl + vbase_idx + (t0_));        \
        CP_COMMIT();                                                    \
    } while (0)

    PREFETCH(0, 0);
    PREFETCH(64, BUF_BYTES);

    float o[4][4];
    #pragma unroll
    for (int on = 0; on < 4; on++)
        #pragma unroll
        for (int e = 0; e < 4; e++) o[on][e] = 0.f;
    float m0 = -1e30f, m1 = -1e30f, l0 = 0.f, l1 = 0.f;

    for (int it = 0; it < 16; it++) {
        if (it == 15) { CP_WAIT(0); } else { CP_WAIT(1); }
        __syncthreads();

        const char* buf = sm_raw + (it & 1) * BUF_BYTES;
        const __nv_bfloat16* kh_s = (const __nv_bfloat16*)(buf + BUF_KH);
        const __nv_bfloat16* kl_s = (const __nv_bfloat16*)(buf + BUF_KL);
        const __nv_bfloat16* vh_s = (const __nv_bfloat16*)(buf + BUF_VH);
        const __nv_bfloat16* vl_s = (const __nv_bfloat16*)(buf + BUF_VL);

        // ---- S = Q K^T (bf16x3), log2-domain logits ----
        float sf[8][4];
        #pragma unroll
        for (int j = 0; j < 8; j++)
            #pragma unroll
            for (int e = 0; e < 4; e++) sf[j][e] = 0.f;

        #pragma unroll
        for (int s = 0; s < 2; s++) {
            const int ko = s * 16 + tig * 2;
            #pragma unroll
            for (int j = 0; j < 8; j++) {
                const __nv_bfloat16* kp = kh_s + (j * 8 + g) * QS + ko;
                const __nv_bfloat16* lp = kl_s + (j * 8 + g) * QS + ko;
                uint32_t bhf[2], blf[2];
                bhf[0] = *(const uint32_t*)(kp);
                bhf[1] = *(const uint32_t*)(kp + 8);
                blf[0] = *(const uint32_t*)(lp);
                blf[1] = *(const uint32_t*)(lp + 8);
                mma_bf16(sf[j], qfh[s], bhf);
                mma_bf16(sf[j], qfl[s], bhf);
                mma_bf16(sf[j], qfh[s], blf);
            }
        }

        // ---- online softmax (exp2 domain), sf overwritten with p ----
        float tmax0 = -1e30f, tmax1 = -1e30f;
        #pragma unroll
        for (int j = 0; j < 8; j++) {
            tmax0 = fmaxf(tmax0, fmaxf(sf[j][0], sf[j][1]));
            tmax1 = fmaxf(tmax1, fmaxf(sf[j][2], sf[j][3]));
        }
        tmax0 = fmaxf(tmax0, __shfl_xor_sync(0xffffffffu, tmax0, 1));
        tmax0 = fmaxf(tmax0, __shfl_xor_sync(0xffffffffu, tmax0, 2));
        tmax1 = fmaxf(tmax1, __shfl_xor_sync(0xffffffffu, tmax1, 1));
        tmax1 = fmaxf(tmax1, __shfl_xor_sync(0xffffffffu, tmax1, 2));

        const float mn0 = fmaxf(m0, tmax0);
        const float mn1 = fmaxf(m1, tmax1);
        const float sc0 = ex2f(m0 - mn0);
        const float sc1 = ex2f(m1 - mn1);
        m0 = mn0; m1 = mn1;
        #pragma unroll
        for (int on = 0; on < 4; on++) {
            o[on][0] *= sc0; o[on][1] *= sc0;
            o[on][2] *= sc1; o[on][3] *= sc1;
        }
        float rs0 = 0.f, rs1 = 0.f;
        #pragma unroll
        for (int j = 0; j < 8; j++) {
            sf[j][0] = ex2f(sf[j][0] - m0);
            sf[j][1] = ex2f(sf[j][1] - m0);
            sf[j][2] = ex2f(sf[j][2] - m1);
            sf[j][3] = ex2f(sf[j][3] - m1);
            rs0 += sf[j][0] + sf[j][1];
            rs1 += sf[j][2] + sf[j][3];
        }
        rs0 += __shfl_xor_sync(0xffffffffu, rs0, 1);
        rs0 += __shfl_xor_sync(0xffffffffu, rs0, 2);
        rs1 += __shfl_xor_sync(0xffffffffu, rs1, 1);
        rs1 += __shfl_xor_sync(0xffffffffu, rs1, 2);
        l0 = l0 * sc0 + rs0;
        l1 = l1 * sc1 + rs1;

        // ---- O += P V (bf16x3) ----
        #pragma unroll
        for (int s = 0; s < 4; s++) {
            const float* pa = sf[2 * s];
            const float* pb = sf[2 * s + 1];
            uint32_t pha[4], pla[4];
            pha[0] = cvt_bf16x2(pa[1], pa[0]);
            pha[1] = cvt_bf16x2(pa[3], pa[2]);
            pha[2] = cvt_bf16x2(pb[1], pb[0]);
            pha[3] = cvt_bf16x2(pb[3], pb[2]);
            {
                float la0 = pa[0] - __bfloat162float(__float2bfloat16(pa[0]));
                float la1 = pa[1] - __bfloat162float(__float2bfloat16(pa[1]));
                float la2 = pa[2] - __bfloat162float(__float2bfloat16(pa[2]));
                float la3 = pa[3] - __bfloat162float(__float2bfloat16(pa[3]));
                float lb0 = pb[0] - __bfloat162float(__float2bfloat16(pb[0]));
                float lb1 = pb[1] - __bfloat162float(__float2bfloat16(pb[1]));
                float lb2 = pb[2] - __bfloat162float(__float2bfloat16(pb[2]));
                float lb3 = pb[3] - __bfloat162float(__float2bfloat16(pb[3]));
                pla[0] = cvt_bf16x2(la1, la0);
                pla[1] = cvt_bf16x2(la3, la2);
                pla[2] = cvt_bf16x2(lb1, lb0);
                pla[3] = cvt_bf16x2(lb3, lb2);
            }
            const int ko = s * 16 + tig * 2;
            #pragma unroll
            for (int on = 0; on < 4; on++) {
                const __nv_bfloat16* vp = vh_s + (on * 8 + g) * VS + ko;
                const __nv_bfloat16* wp = vl_s + (on * 8 + g) * VS + ko;
                uint32_t bvh[2], bvl[2];
                bvh[0] = *(const uint32_t*)(vp);
                bvh[1] = *(const uint32_t*)(vp + 8);
                bvl[0] = *(const uint32_t*)(wp);
                bvl[1] = *(const uint32_t*)(wp + 8);
                mma_bf16(o[on], pha, bvh);
                mma_bf16(o[on], pla, bvh);
                mma_bf16(o[on], pha, bvl);
            }
        }

        __syncthreads();
        if (it + 2 < 16) {
            PREFETCH((it + 2) * 64, (it & 1) * BUF_BYTES);
        }
    }

    // ---- epilogue: unnormalized O + m/l straight to global ----
    {
        const size_t b0 = ((size_t)bh * NTOK + n0 + row) * DHEAD;
        const size_t b1 = ((size_t)bh * NTOK + n0 + row + 8) * DHEAD;
        #pragma unroll
        for (int on = 0; on < 4; on++) {
            *(float2*)(g_oacc + b0 + on * 8 + tig * 2) =
                make_float2(o[on][0], o[on][1]);
            *(float2*)(g_oacc + b1 + on * 8 + tig * 2) =
                make_float2(o[on][2], o[on][3]);
        }
        if (tig == 0) {
            g_om[bh * NTOK + n0 + row]     = m0;
            g_ol[bh * NTOK + n0 + row]     = l0;
            g_om[bh * NTOK + n0 + row + 8] = m1;
            g_ol[bh * NTOK + n0 + row + 8] = l1;
        }
    }
}

// ---------------------------------------------------------------------------
// Kernel 3b: local 3x3 merge + normalize + ctx hi/lo store (scalar fp32)
// grid (8,8,8), 128 threads; thread = one query.
// ---------------------------------------------------------------------------
__global__ __launch_bounds__(128) void local_merge_kernel()
{
    const int tid = threadIdx.x;
    const int bh  = blockIdx.z * N_HEADS + blockIdx.y;
    const int n   = blockIdx.x * 128 + tid;

    float m = g_om[bh * NTOK + n];
    float l = g_ol[bh * NTOK + n];

    u64 qv[16];
    {
        const float* qp = g_q + ((size_t)bh * NTOK + n) * DHEAD;
        #pragma unroll
        for (int d = 0; d < 16; d++) {
            float2 t2 = ((const float2*)qp)[d];
            qv[d] = pack2(t2.x * QSCALE, t2.y * QSCALE);
        }
    }
    u64 acc2[16];
    {
        const float* op = g_oacc + ((size_t)bh * NTOK + n) * DHEAD;
        #pragma unroll
        for (int d = 0; d < 16; d++) {
            float2 t2 = ((const float2*)op)[d];
            acc2[d] = pack2(t2.x, t2.y);
        }
    }

    const float* klb = g_kl + (size_t)bh * NTOK * DHEAD;
    const float* vlb = g_vl + (size_t)bh * NTOK * DHEAD;
    const int qi = n >> 5, qj = n & 31;

    float sl[9];
    int   gl[9];
    int   cnt  = 0;
    float lmax = -1e30f;
    #pragma unroll
    for (int oi = -1; oi <= 1; oi++) {
        #pragma unroll
        for (int oj = -1; oj <= 1; oj++) {
            int ni = qi + oi, nj = qj + oj;
            if (ni < 0 || ni >= IMG || nj < 0 || nj >= IMG) continue;
            int gg = ni * IMG + nj;
            const ulonglong2* kk8 = (const ulonglong2*)(klb + (size_t)gg * DHEAD);
            u64 s0 = 0ull, s1 = 0ull;
            #pragma unroll
            for (int d = 0; d < 8; d++) {
                ulonglong2 kk = kk8[d];
                ffma2(s0, qv[2 * d],     kk.x);
                ffma2(s1, qv[2 * d + 1], kk.y);
            }
            float2 f0 = unpack2(s0);
            float2 f1 = unpack2(s1);
            float s = (f0.x + f0.y) + (f1.x + f1.y);
            sl[cnt] = s;
            gl[cnt] = gg;
            cnt++;
            lmax = fmaxf(lmax, s);
        }
    }

    float mnew  = fmaxf(m, lmax);
    float scale = ex2f(m - mnew);
    l *= scale;
    #pragma unroll
    for (int d = 0; d < 16; d++) {
        float2 f = unpack2(acc2[d]);
        acc2[d] = pack2(f.x * scale, f.y * scale);
    }
    m = mnew;

    for (int c = 0; c < cnt; c++) {
        float p = ex2f(sl[c] - m);
        l += p;
        u64 pp = pack2(p, p);
        const ulonglong2* vv8 = (const ulonglong2*)(vlb + (size_t)gl[c] * DHEAD);
        #pragma unroll
        for (int d = 0; d < 8; d++) {
            ffma2(acc2[2 * d],     pp, vv8[d].x);
            ffma2(acc2[2 * d + 1], pp, vv8[d].y);
        }
    }

    const float inv = 1.0f / l;
    const size_t obase = ((size_t)(blockIdx.z * NTOK + n)) * D_MODEL
                       + blockIdx.y * DHEAD;
    __nv_bfloat162* ph = (__nv_bfloat162*)(g_ctxh + obase);
    __nv_bfloat162* pl = (__nv_bfloat162*)(g_ctxl + obase);
    #pragma unroll
    for (int d = 0; d < 16; d++) {
        float2 f = unpack2(acc2[d]);
        f.x *= inv; f.y *= inv;
        __nv_bfloat16 h0 = __float2bfloat16(f.x);
        __nv_bfloat16 h1 = __float2bfloat16(f.y);
        ph[d] = __halves2bfloat162(h0, h1);
        pl[d] = __halves2bfloat162(
            __float2bfloat16(f.x - __bfloat162float(h0)),
            __float2bfloat16(f.y - __bfloat162float(h1)));
    }
}

// ---------------------------------------------------------------------------
extern "C" void kernel_launch(void* const* d_in, const int* in_sizes, int n_in,
                              void* d_out, int out_size)
{
    const float* x     = (const float*)d_in[0];
    const float* gamma = (const float*)d_in[1];
    const float* beta  = (const float*)d_in[2];
    const float* Wq    = (const float*)d_in[3];
    const float* Wk    = (const float*)d_in[4];
    const float* Wv    = (const float*)d_in[5];
    const float* Wkl   = (const float*)d_in[6];
    const float* Wvl   = (const float*)d_in[7];
    const float* Wo    = (const float*)d_in[8];
    const float* qb    = (const float*)d_in[9];
    float* out = (float*)d_out;

    cudaFuncSetAttribute(gemm_mma_kernel,
                         cudaFuncAttributeMaxDynamicSharedMemorySize,
                         GEMM_SMEM_BYTES);
    cudaFuncSetAttribute(attn_mma_kernel,
                         cudaFuncAttributeMaxDynamicSharedMemorySize,
                         ATTN_SMEM_BYTES);

    wprep_kernel<<<1536, 256>>>(Wq, Wk, Wv, Wkl, Wvl, Wo);
    ln_kernel<<<NROWS, 256>>>(x, gamma, beta);
    gemm_mma_kernel<<<dim3(2, 64, 5), 256, GEMM_SMEM_BYTES>>>(qb, nullptr, 0);
    attn_mma_kernel<<<dim3(8, 8, 8), 256, ATTN_SMEM_BYTES>>>();
    local_merge_kernel<<<dim3(8, 8, 8), 128>>>();
    gemm_mma_kernel<<<dim3(2, 64, 1), 256, GEMM_SMEM_BYTES>>>(qb, out, 5);
}

// round 8
// speedup vs baseline: 1.1143x; 1.1143x over previous
#include <cuda_runtime.h>
#include <cuda_bf16.h>
#include <cstdint>

// ---------------------------------------------------------------------------
// SpatialLocalAwareAttention — fused-local-epilogue round
// B=2, T=4, H=W=32, D=256, heads=8, dh=32, local 3x3
// ---------------------------------------------------------------------------

#define D_MODEL 256
#define N_HEADS 8
#define DHEAD   32
#define BTDIM   8
#define NTOK    1024
#define NROWS   (BTDIM * NTOK)   // 8192
#define IMG     32

typedef unsigned long long u64;

// ---------------- mma / misc helpers ----------------
__device__ __forceinline__ void mma_bf16(float* c, const uint32_t* a,
                                         const uint32_t* b)
{
    asm volatile(
        "mma.sync.aligned.m16n8k16.row.col.f32.bf16.bf16.f32 "
        "{%0,%1,%2,%3}, {%4,%5,%6,%7}, {%8,%9}, {%0,%1,%2,%3};"
        : "+f"(c[0]), "+f"(c[1]), "+f"(c[2]), "+f"(c[3])
        : "r"(a[0]), "r"(a[1]), "r"(a[2]), "r"(a[3]),
          "r"(b[0]), "r"(b[1]));
}
__device__ __forceinline__ uint32_t cvt_bf16x2(float hi, float lo) {
    uint32_t r;
    asm("cvt.rn.bf16x2.f32 %0, %1, %2;" : "=r"(r) : "f"(hi), "f"(lo));
    return r;
}
__device__ __forceinline__ float ex2f(float x) {
    float r; asm("ex2.approx.f32 %0, %1;" : "=f"(r) : "f"(x)); return r;
}
__device__ __forceinline__ uint32_t smem_u32(const void* p) {
    uint32_t a;
    asm("{ .reg .u64 t; cvta.to.shared.u64 t, %1; cvt.u32.u64 %0, t; }"
        : "=r"(a) : "l"(p));
    return a;
}
__device__ __forceinline__ void cp_async16(uint32_t dst, const void* src) {
    asm volatile("cp.async.cg.shared.global [%0], [%1], 16;"
                 :: "r"(dst), "l"(__cvta_generic_to_global(src)) : "memory");
}
#define CP_COMMIT() asm volatile("cp.async.commit_group;" ::: "memory")
#define CP_WAIT(n)  asm volatile("cp.async.wait_group %0;" :: "n"(n) : "memory")

// scale folded into Q: softmax computed in exp2 domain (exact base change)
#define QSCALE (0.17677669529663687f * 1.4426950408889634f)

// ---------------- global scratch ----------------
__device__ __align__(16) __nv_bfloat16 g_xnh [NROWS * D_MODEL];
__device__ __align__(16) __nv_bfloat16 g_xnl [NROWS * D_MODEL];
__device__ __align__(16) __nv_bfloat16 g_ctxh[NROWS * D_MODEL];
__device__ __align__(16) __nv_bfloat16 g_ctxl[NROWS * D_MODEL];
__device__ __align__(16) __nv_bfloat16 g_wh  [6 * D_MODEL * D_MODEL];
__device__ __align__(16) __nv_bfloat16 g_wl  [6 * D_MODEL * D_MODEL];

__device__ float g_q  [NROWS * D_MODEL];                 // fp32 q (+bias)
__device__ float g_kl [NROWS * D_MODEL];                 // fp32 local k
__device__ float g_vl [NROWS * D_MODEL];                 // fp32 local v
__device__ __align__(16) __nv_bfloat16 g_kbh[NROWS * D_MODEL];
__device__ __align__(16) __nv_bfloat16 g_kbl[NROWS * D_MODEL];
__device__ __align__(16) __nv_bfloat16 g_vth[NROWS * D_MODEL];   // v transposed
__device__ __align__(16) __nv_bfloat16 g_vtl[NROWS * D_MODEL];

// ---------------------------------------------------------------------------
// Kernel 0: weights -> bf16 hi/lo
// ---------------------------------------------------------------------------
__global__ __launch_bounds__(256) void wprep_kernel(const float* __restrict__ Wq,
                                                    const float* __restrict__ Wk,
                                                    const float* __restrict__ Wv,
                                                    const float* __restrict__ Wkl,
                                                    const float* __restrict__ Wvl,
                                                    const float* __restrict__ Wo)
{
    int idx = blockIdx.x * 256 + threadIdx.x;
    int z = idx >> 16;
    const float* Ws;
    switch (z) {
        case 0: Ws = Wq;  break;
        case 1: Ws = Wk;  break;
        case 2: Ws = Wv;  break;
        case 3: Ws = Wkl; break;
        case 4: Ws = Wvl; break;
        default: Ws = Wo; break;
    }
    float a = Ws[idx & 65535];
    __nv_bfloat16 hi = __float2bfloat16(a);
    g_wh[idx] = hi;
    g_wl[idx] = __float2bfloat16(a - __bfloat162float(hi));
}

// ---------------------------------------------------------------------------
// Kernel 1: layernorm + gather; emits bf16 hi/lo of xn
// ---------------------------------------------------------------------------
__global__ __launch_bounds__(256) void ln_kernel(const float* __restrict__ x,
                                                 const float* __restrict__ gamma,
                                                 const float* __restrict__ beta)
{
    int row = blockIdx.x;
    int d   = threadIdx.x;
    int bt  = row >> 10;
    int n   = row & 1023;
    int b   = bt >> 2;
    int t   = bt & 3;

    float v = x[((size_t)(b * D_MODEL + d) * 4 + t) * 1024 + n];

    float s  = v;
    float s2 = v * v;
    #pragma unroll
    for (int off = 16; off > 0; off >>= 1) {
        s  += __shfl_down_sync(0xffffffffu, s,  off);
        s2 += __shfl_down_sync(0xffffffffu, s2, off);
    }
    __shared__ float ws[8], ws2[8];
    __shared__ float mu_s, rstd_s;
    int lane = d & 31, wid = d >> 5;
    if (lane == 0) { ws[wid] = s; ws2[wid] = s2; }
    __syncthreads();
    if (d == 0) {
        float a = 0.f, b2 = 0.f;
        #pragma unroll
        for (int w = 0; w < 8; w++) { a += ws[w]; b2 += ws2[w]; }
        float mu  = a * (1.0f / 256.0f);
        float var = b2 * (1.0f / 256.0f) - mu * mu;
        mu_s   = mu;
        rstd_s = rsqrtf(var + 1e-6f);
    }
    __syncthreads();
    float xnv = (v - mu_s) * rstd_s * gamma[d] + beta[d];
    __nv_bfloat16 hi = __float2bfloat16(xnv);
    g_xnh[(size_t)row * 256 + d] = hi;
    g_xnl[(size_t)row * 256 + d] = __float2bfloat16(xnv - __bfloat162float(hi));
}

// ---------------------------------------------------------------------------
// Kernel 2/4: bf16x3 mma.sync GEMM (validated), per-z epilogues.
// ---------------------------------------------------------------------------
#define ASTR 72
#define GEMM_SMEM_BYTES (4 * 128 * ASTR * 2)   // 73728

__global__ __launch_bounds__(256) void gemm_mma_kernel(const float* __restrict__ qb,
                                                       float* __restrict__ out,
                                                       int z_base)
{
    extern __shared__ __nv_bfloat16 smem[];
    __nv_bfloat16* sAh = smem;
    __nv_bfloat16* sAl = smem + 128 * ASTR;
    __nv_bfloat16* sBh = smem + 2 * 128 * ASTR;
    __nv_bfloat16* sBl = smem + 3 * 128 * ASTR;

    const int tid  = threadIdx.x;
    const int wid  = tid >> 5;
    const int lane = tid & 31;
    const int z    = blockIdx.z + z_base;
    const int m0   = blockIdx.y * 128;
    const int cg0  = blockIdx.x * 128;

    const __nv_bfloat16* Ah = (z < 5) ? g_xnh : g_ctxh;
    const __nv_bfloat16* Al = (z < 5) ? g_xnl : g_ctxl;
    const __nv_bfloat16* Bh = g_wh + (size_t)z * 65536;
    const __nv_bfloat16* Bl = g_wl + (size_t)z * 65536;

    const int wm = (wid >> 2) * 64;
    const int wn = (wid & 3) * 32;
    const int g   = lane >> 2;
    const int tig = lane & 3;

    float acc[4][4][4];
    #pragma unroll
    for (int i = 0; i < 4; i++)
        #pragma unroll
        for (int j = 0; j < 4; j++)
            #pragma unroll
            for (int e = 0; e < 4; e++) acc[i][j][e] = 0.f;

    const int lrow = tid >> 1;
    const int lhalf = (tid & 1) * 32;

    for (int k0 = 0; k0 < 256; k0 += 64) {
        __syncthreads();
        {
            const uint4* gah = (const uint4*)(Ah + (size_t)(m0 + lrow) * 256 + k0 + lhalf);
            const uint4* gal = (const uint4*)(Al + (size_t)(m0 + lrow) * 256 + k0 + lhalf);
            const uint4* gbh = (const uint4*)(Bh + (size_t)(cg0 + lrow) * 256 + k0 + lhalf);
            const uint4* gbl = (const uint4*)(Bl + (size_t)(cg0 + lrow) * 256 + k0 + lhalf);
            uint4* dah = (uint4*)(sAh + lrow * ASTR + lhalf);
            uint4* dal = (uint4*)(sAl + lrow * ASTR + lhalf);
            uint4* dbh = (uint4*)(sBh + lrow * ASTR + lhalf);
            uint4* dbl = (uint4*)(sBl + lrow * ASTR + lhalf);
            #pragma unroll
            for (int q = 0; q < 4; q++) {
                dah[q] = gah[q];
                dal[q] = gal[q];
                dbh[q] = gbh[q];
                dbl[q] = gbl[q];
            }
        }
        __syncthreads();

        #pragma unroll
        for (int ks = 0; ks < 4; ks++) {
            const int koff = ks * 16;
            uint32_t ah[4][4], al[4][4];
            #pragma unroll
            for (int i = 0; i < 4; i++) {
                const int r0 = wm + i * 16 + g;
                const __nv_bfloat16* ph0 = sAh + r0 * ASTR + koff + tig * 2;
                const __nv_bfloat16* ph1 = ph0 + 8 * ASTR;
                const __nv_bfloat16* pl0 = sAl + r0 * ASTR + koff + tig * 2;
                const __nv_bfloat16* pl1 = pl0 + 8 * ASTR;
                ah[i][0] = *(const uint32_t*)(ph0);
                ah[i][1] = *(const uint32_t*)(ph1);
                ah[i][2] = *(const uint32_t*)(ph0 + 8);
                ah[i][3] = *(const uint32_t*)(ph1 + 8);
                al[i][0] = *(const uint32_t*)(pl0);
                al[i][1] = *(const uint32_t*)(pl1);
                al[i][2] = *(const uint32_t*)(pl0 + 8);
                al[i][3] = *(const uint32_t*)(pl1 + 8);
            }
            #pragma unroll
            for (int j = 0; j < 4; j++) {
                const int nb = wn + j * 8 + g;
                const __nv_bfloat16* pb = sBh + nb * ASTR + koff + tig * 2;
                const __nv_bfloat16* pc = sBl + nb * ASTR + koff + tig * 2;
                uint32_t bh[2], bl[2];
                bh[0] = *(const uint32_t*)(pb);
                bh[1] = *(const uint32_t*)(pb + 8);
                bl[0] = *(const uint32_t*)(pc);
                bl[1] = *(const uint32_t*)(pc + 8);
                #pragma unroll
                for (int i = 0; i < 4; i++) {
                    mma_bf16(acc[i][j], ah[i], bh);
                    mma_bf16(acc[i][j], ah[i], bl);
                    mma_bf16(acc[i][j], al[i], bh);
                }
            }
        }
    }

    // ---- epilogue ----
    if (z == 5) {
        #pragma unroll
        for (int i = 0; i < 4; i++) {
            const int mlo = m0 + wm + i * 16 + g;
            const int mhi = mlo + 8;
            const int bt_ = mlo >> 10;
            const int b   = bt_ >> 2;
            const int t   = bt_ & 3;
            const int nlo = mlo & 1023;
            const int nhi = mhi & 1023;
            #pragma unroll
            for (int j = 0; j < 4; j++) {
                const int cc = cg0 + wn + j * 8 + tig * 2;
                out[((size_t)((b * D_MODEL + cc)     * 4 + t)) * 1024 + nlo] = acc[i][j][0];
                out[((size_t)((b * D_MODEL + cc + 1) * 4 + t)) * 1024 + nlo] = acc[i][j][1];
                out[((size_t)((b * D_MODEL + cc)     * 4 + t)) * 1024 + nhi] = acc[i][j][2];
                out[((size_t)((b * D_MODEL + cc + 1) * 4 + t)) * 1024 + nhi] = acc[i][j][3];
            }
        }
        return;
    }

    #pragma unroll
    for (int i = 0; i < 4; i++) {
        const int mlo = m0 + wm + i * 16 + g;
        const int mhi = mlo + 8;
        const int bt_ = mlo >> 10;
        const int nlo = mlo & 1023;
        const int nhi = mhi & 1023;
        #pragma unroll
        for (int j = 0; j < 4; j++) {
            const int cc   = cg0 + wn + j * 8 + tig * 2;
            const int head = cc >> 5;
            const int dh0  = cc & 31;
            const int bh2  = bt_ * N_HEADS + head;

            if (z == 0) {
                float b0 = qb[cc], b1 = qb[cc + 1];
                float* base = g_q + ((size_t)bh2 * NTOK) * DHEAD + dh0;
                *(float2*)(base + (size_t)nlo * DHEAD) =
                    make_float2(acc[i][j][0] + b0, acc[i][j][1] + b1);
                *(float2*)(base + (size_t)nhi * DHEAD) =
                    make_float2(acc[i][j][2] + b0, acc[i][j][3] + b1);
            } else if (z == 1) {
                size_t base = ((size_t)bh2 * NTOK) * DHEAD + dh0;
                #pragma unroll
                for (int half = 0; half < 2; half++) {
                    const int nn = half ? nhi : nlo;
                    float v0 = acc[i][j][half * 2];
                    float v1 = acc[i][j][half * 2 + 1];
                    __nv_bfloat16 h0 = __float2bfloat16(v0);
                    __nv_bfloat16 h1 = __float2bfloat16(v1);
                    *(__nv_bfloat162*)(g_kbh + base + (size_t)nn * DHEAD) =
                        __halves2bfloat162(h0, h1);
                    *(__nv_bfloat162*)(g_kbl + base + (size_t)nn * DHEAD) =
                        __halves2bfloat162(
                            __float2bfloat16(v0 - __bfloat162float(h0)),
                            __float2bfloat16(v1 - __bfloat162float(h1)));
                }
            } else if (z == 2) {
                #pragma unroll
                for (int half = 0; half < 2; half++) {
                    const int nn = half ? nhi : nlo;
                    float v0 = acc[i][j][half * 2];
                    float v1 = acc[i][j][half * 2 + 1];
                    __nv_bfloat16 h0 = __float2bfloat16(v0);
                    __nv_bfloat16 h1 = __float2bfloat16(v1);
                    size_t i0 = ((size_t)bh2 * DHEAD + dh0) * NTOK + nn;
                    size_t i1 = ((size_t)bh2 * DHEAD + dh0 + 1) * NTOK + nn;
                    g_vth[i0] = h0;
                    g_vth[i1] = h1;
                    g_vtl[i0] = __float2bfloat16(v0 - __bfloat162float(h0));
                    g_vtl[i1] = __float2bfloat16(v1 - __bfloat162float(h1));
                }
            } else {
                float* dst = (z == 3) ? g_kl : g_vl;
                float* base = dst + ((size_t)bh2 * NTOK) * DHEAD + dh0;
                *(float2*)(base + (size_t)nlo * DHEAD) =
                    make_float2(acc[i][j][0], acc[i][j][1]);
                *(float2*)(base + (size_t)nhi * DHEAD) =
                    make_float2(acc[i][j][2], acc[i][j][3]);
            }
        }
    }
}

// ---------------------------------------------------------------------------
// Kernel 3: flash attention, Q in regs, cp.async ping-pong, exp2 softmax,
// fused fragment-layout 3x3 local merge in the epilogue, direct ctx store.
// ---------------------------------------------------------------------------
#define QS 40
#define VS 72
#define BUF_KH   0
#define BUF_KL   (64 * QS * 2)
#define BUF_VH   (2 * 64 * QS * 2)
#define BUF_VL   (BUF_VH + 32 * VS * 2)
#define BUF_BYTES (BUF_VL + 32 * VS * 2)       // 19456
#define ATTN_SMEM_BYTES (2 * BUF_BYTES)        // 38912

__global__ __launch_bounds__(256, 3) void attn_mma_kernel()
{
    extern __shared__ char sm_raw[];

    const int tid  = threadIdx.x;
    const int wid  = tid >> 5;
    const int lane = tid & 31;
    const int g    = lane >> 2;
    const int tig  = lane & 3;
    const int bh   = blockIdx.z * N_HEADS + blockIdx.y;
    const int n0   = blockIdx.x * 128;

    const int row = wid * 16 + g;

    // ---- Q fragments in registers (scaled by QSCALE, hi/lo split) ----
    uint32_t qfh[2][4], qfl[2][4];
    {
        const float* qbase = g_q + ((size_t)bh * NTOK + n0) * DHEAD;
        #pragma unroll
        for (int s = 0; s < 2; s++) {
            const int ko = s * 16 + tig * 2;
            #pragma unroll
            for (int e = 0; e < 4; e++) {
                const int rr  = row + (e & 1) * 8;
                const int col = ko + (e >> 1) * 8;
                float2 v = *(const float2*)(qbase + (size_t)rr * DHEAD + col);
                v.x *= QSCALE; v.y *= QSCALE;
                __nv_bfloat16 h0 = __float2bfloat16(v.x);
                __nv_bfloat16 h1 = __float2bfloat16(v.y);
                qfh[s][e] = cvt_bf16x2(v.y, v.x);
                qfl[s][e] = cvt_bf16x2(v.y - __bfloat162float(h1),
                                       v.x - __bfloat162float(h0));
            }
        }
    }

    // ---- per-thread cp.async slots ----
    const int key = tid >> 2, dofk = (tid & 3) * 8;
    const int vd  = tid >> 3, kofv = (tid & 7) * 8;
    const size_t kbase_idx = ((size_t)bh * NTOK + key) * DHEAD + dofk;
    const size_t vbase_idx = ((size_t)bh * DHEAD + vd) * NTOK + kofv;
    const uint32_t sm_base = smem_u32(sm_raw);
    const uint32_t kh_dst = sm_base + BUF_KH + (key * QS + dofk) * 2;
    const uint32_t kl_dst = sm_base + BUF_KL + (key * QS + dofk) * 2;
    const uint32_t vh_dst = sm_base + BUF_VH + (vd * VS + kofv) * 2;
    const uint32_t vl_dst = sm_base + BUF_VL + (vd * VS + kofv) * 2;

    #define PREFETCH(t0_, bofs_) do {                                   \
        cp_async16(kh_dst + (bofs_), g_kbh + kbase_idx + (size_t)(t0_) * DHEAD); \
        cp_async16(kl_dst + (bofs_), g_kbl + kbase_idx + (size_t)(t0_) * DHEAD); \
        cp_async16(vh_dst + (bofs_), g_vth + vbase_idx + (t0_));        \
        cp_async16(vl_dst + (bofs_), g_vtl + vbase_idx + (t0_));        \
        CP_COMMIT();                                                    \
    } while (0)

    PREFETCH(0, 0);
    PREFETCH(64, BUF_BYTES);

    float o[4][4];
    #pragma unroll
    for (int on = 0; on < 4; on++)
        #pragma unroll
        for (int e = 0; e < 4; e++) o[on][e] = 0.f;
    float m0 = -1e30f, m1 = -1e30f, l0 = 0.f, l1 = 0.f;

    for (int it = 0; it < 16; it++) {
        if (it == 15) { CP_WAIT(0); } else { CP_WAIT(1); }
        __syncthreads();

        const char* buf = sm_raw + (it & 1) * BUF_BYTES;
        const __nv_bfloat16* kh_s = (const __nv_bfloat16*)(buf + BUF_KH);
        const __nv_bfloat16* kl_s = (const __nv_bfloat16*)(buf + BUF_KL);
        const __nv_bfloat16* vh_s = (const __nv_bfloat16*)(buf + BUF_VH);
        const __nv_bfloat16* vl_s = (const __nv_bfloat16*)(buf + BUF_VL);

        // ---- S = Q K^T (bf16x3), log2-domain logits ----
        float sf[8][4];
        #pragma unroll
        for (int j = 0; j < 8; j++)
            #pragma unroll
            for (int e = 0; e < 4; e++) sf[j][e] = 0.f;

        #pragma unroll
        for (int s = 0; s < 2; s++) {
            const int ko = s * 16 + tig * 2;
            #pragma unroll
            for (int j = 0; j < 8; j++) {
                const __nv_bfloat16* kp = kh_s + (j * 8 + g) * QS + ko;
                const __nv_bfloat16* lp = kl_s + (j * 8 + g) * QS + ko;
                uint32_t bhf[2], blf[2];
                bhf[0] = *(const uint32_t*)(kp);
                bhf[1] = *(const uint32_t*)(kp + 8);
                blf[0] = *(const uint32_t*)(lp);
                blf[1] = *(const uint32_t*)(lp + 8);
                mma_bf16(sf[j], qfh[s], bhf);
                mma_bf16(sf[j], qfl[s], bhf);
                mma_bf16(sf[j], qfh[s], blf);
            }
        }

        // ---- online softmax (exp2 domain), sf overwritten with p ----
        float tmax0 = -1e30f, tmax1 = -1e30f;
        #pragma unroll
        for (int j = 0; j < 8; j++) {
            tmax0 = fmaxf(tmax0, fmaxf(sf[j][0], sf[j][1]));
            tmax1 = fmaxf(tmax1, fmaxf(sf[j][2], sf[j][3]));
        }
        tmax0 = fmaxf(tmax0, __shfl_xor_sync(0xffffffffu, tmax0, 1));
        tmax0 = fmaxf(tmax0, __shfl_xor_sync(0xffffffffu, tmax0, 2));
        tmax1 = fmaxf(tmax1, __shfl_xor_sync(0xffffffffu, tmax1, 1));
        tmax1 = fmaxf(tmax1, __shfl_xor_sync(0xffffffffu, tmax1, 2));

        const float mn0 = fmaxf(m0, tmax0);
        const float mn1 = fmaxf(m1, tmax1);
        const float sc0 = ex2f(m0 - mn0);
        const float sc1 = ex2f(m1 - mn1);
        m0 = mn0; m1 = mn1;
        #pragma unroll
        for (int on = 0; on < 4; on++) {
            o[on][0] *= sc0; o[on][1] *= sc0;
            o[on][2] *= sc1; o[on][3] *= sc1;
        }
        float rs0 = 0.f, rs1 = 0.f;
        #pragma unroll
        for (int j = 0; j < 8; j++) {
            sf[j][0] = ex2f(sf[j][0] - m0);
            sf[j][1] = ex2f(sf[j][1] - m0);
            sf[j][2] = ex2f(sf[j][2] - m1);
            sf[j][3] = ex2f(sf[j][3] - m1);
            rs0 += sf[j][0] + sf[j][1];
            rs1 += sf[j][2] + sf[j][3];
        }
        rs0 += __shfl_xor_sync(0xffffffffu, rs0, 1);
        rs0 += __shfl_xor_sync(0xffffffffu, rs0, 2);
        rs1 += __shfl_xor_sync(0xffffffffu, rs1, 1);
        rs1 += __shfl_xor_sync(0xffffffffu, rs1, 2);
        l0 = l0 * sc0 + rs0;
        l1 = l1 * sc1 + rs1;

        // ---- O += P V (bf16x3) ----
        #pragma unroll
        for (int s = 0; s < 4; s++) {
            const float* pa = sf[2 * s];
            const float* pb = sf[2 * s + 1];
            uint32_t pha[4], pla[4];
            pha[0] = cvt_bf16x2(pa[1], pa[0]);
            pha[1] = cvt_bf16x2(pa[3], pa[2]);
            pha[2] = cvt_bf16x2(pb[1], pb[0]);
            pha[3] = cvt_bf16x2(pb[3], pb[2]);
            {
                float la0 = pa[0] - __bfloat162float(__float2bfloat16(pa[0]));
                float la1 = pa[1] - __bfloat162float(__float2bfloat16(pa[1]));
                float la2 = pa[2] - __bfloat162float(__float2bfloat16(pa[2]));
                float la3 = pa[3] - __bfloat162float(__float2bfloat16(pa[3]));
                float lb0 = pb[0] - __bfloat162float(__float2bfloat16(pb[0]));
                float lb1 = pb[1] - __bfloat162float(__float2bfloat16(pb[1]));
                float lb2 = pb[2] - __bfloat162float(__float2bfloat16(pb[2]));
                float lb3 = pb[3] - __bfloat162float(__float2bfloat16(pb[3]));
                pla[0] = cvt_bf16x2(la1, la0);
                pla[1] = cvt_bf16x2(la3, la2);
                pla[2] = cvt_bf16x2(lb1, lb0);
                pla[3] = cvt_bf16x2(lb3, lb2);
            }
            const int ko = s * 16 + tig * 2;
            #pragma unroll
            for (int on = 0; on < 4; on++) {
                const __nv_bfloat16* vp = vh_s + (on * 8 + g) * VS + ko;
                const __nv_bfloat16* wp = vl_s + (on * 8 + g) * VS + ko;
                uint32_t bvh[2], bvl[2];
                bvh[0] = *(const uint32_t*)(vp);
                bvh[1] = *(const uint32_t*)(vp + 8);
                bvl[0] = *(const uint32_t*)(wp);
                bvl[1] = *(const uint32_t*)(wp + 8);
                mma_bf16(o[on], pha, bvh);
                mma_bf16(o[on], pla, bvh);
                mma_bf16(o[on], pha, bvl);
            }
        }

        __syncthreads();
        if (it + 2 < 16) {
            PREFETCH((it + 2) * 64, (it & 1) * BUF_BYTES);
        }
    }

    // ---- fused local 3x3 merge (fragment layout) + normalize + ctx ----
    const float* klb = g_kl + (size_t)bh * NTOK * DHEAD;
    const float* vlb = g_vl + (size_t)bh * NTOK * DHEAD;

    #pragma unroll
    for (int half = 0; half < 2; half++) {
        const int n  = n0 + row + half * 8;
        const int qi = n >> 5, qj = n & 31;
        float m = half ? m1 : m0;
        float l = half ? l1 : l0;

        const float2* qq = (const float2*)(g_q + ((size_t)bh * NTOK + n) * DHEAD
                                           + tig * 8);
        float2 q0 = qq[0], q1 = qq[1], q2 = qq[2], q3 = qq[3];

        float sl[9];
        float lmax = -1e30f;
        #pragma unroll
        for (int k = 0; k < 9; k++) {
            const int oi = k / 3 - 1, oj = k % 3 - 1;
            const int ni = qi + oi, nj = qj + oj;
            const bool valid = (ni >= 0) && (ni < IMG) && (nj >= 0) && (nj < IMG);
            const int ci = min(max(ni, 0), IMG - 1);
            const int cj = min(max(nj, 0), IMG - 1);
            const int gg = ci * IMG + cj;
            const float2* kk = (const float2*)(klb + (size_t)gg * DHEAD + tig * 8);
            float2 k0 = kk[0], k1 = kk[1], k2 = kk[2], k3 = kk[3];
            float acc = q0.x * k0.x + q0.y * k0.y
                      + q1.x * k1.x + q1.y * k1.y
                      + q2.x * k2.x + q2.y * k2.y
                      + q3.x * k3.x + q3.y * k3.y;
            acc += __shfl_xor_sync(0xffffffffu, acc, 1);
            acc += __shfl_xor_sync(0xffffffffu, acc, 2);
            sl[k] = valid ? acc * QSCALE : -1e30f;
            lmax = fmaxf(lmax, sl[k]);
        }

        const float mnew = fmaxf(m, lmax);
        const float sc   = ex2f(m - mnew);
        l *= sc;
        #pragma unroll
        for (int on = 0; on < 4; on++) {
            o[on][half * 2]     *= sc;
            o[on][half * 2 + 1] *= sc;
        }
        m = mnew;

        #pragma unroll
        for (int k = 0; k < 9; k++) {
            const float p = ex2f(sl[k] - m);   // invalid -> exactly 0
            l += p;
            const int oi = k / 3 - 1, oj = k % 3 - 1;
            const int ci = min(max(qi + oi, 0), IMG - 1);
            const int cj = min(max(qj + oj, 0), IMG - 1);
            const float* vb = vlb + (size_t)(ci * IMG + cj) * DHEAD + tig * 2;
            #pragma unroll
            for (int on = 0; on < 4; on++) {
                float2 vv = *(const float2*)(vb + on * 8);
                o[on][half * 2]     += p * vv.x;
                o[on][half * 2 + 1] += p * vv.y;
            }
        }

        // ---- normalize + direct ctx hi/lo store ----
        const float inv = 1.0f / l;
        const size_t obase = ((size_t)(blockIdx.z * NTOK + n)) * D_MODEL
                           + blockIdx.y * DHEAD + tig * 2;
        #pragma unroll
        for (int on = 0; on < 4; on++) {
            float x0 = o[on][half * 2]     * inv;
            float x1 = o[on][half * 2 + 1] * inv;
            __nv_bfloat16 h0 = __float2bfloat16(x0);
            __nv_bfloat16 h1 = __float2bfloat16(x1);
            *(__nv_bfloat162*)(g_ctxh + obase + on * 8) =
                __halves2bfloat162(h0, h1);
            *(__nv_bfloat162*)(g_ctxl + obase + on * 8) =
                __halves2bfloat162(
                    __float2bfloat16(x0 - __bfloat162float(h0)),
                    __float2bfloat16(x1 - __bfloat162float(h1)));
        }
    }
}

// ---------------------------------------------------------------------------
extern "C" void kernel_launch(void* const* d_in, const int* in_sizes, int n_in,
                              void* d_out, int out_size)
{
    const float* x     = (const float*)d_in[0];
    const float* gamma = (const float*)d_in[1];
    const float* beta  = (const float*)d_in[2];
    const float* Wq    = (const float*)d_in[3];
    const float* Wk    = (const float*)d_in[4];
    const float* Wv    = (const float*)d_in[5];
    const float* Wkl   = (const float*)d_in[6];
    const float* Wvl   = (const float*)d_in[7];
    const float* Wo    = (const float*)d_in[8];
    const float* qb    = (const float*)d_in[9];
    float* out = (float*)d_out;

    cudaFuncSetAttribute(gemm_mma_kernel,
                         cudaFuncAttributeMaxDynamicSharedMemorySize,
                         GEMM_SMEM_BYTES);
    cudaFuncSetAttribute(attn_mma_kernel,
                         cudaFuncAttributeMaxDynamicSharedMemorySize,
                         ATTN_SMEM_BYTES);

    wprep_kernel<<<1536, 256>>>(Wq, Wk, Wv, Wkl, Wvl, Wo);
    ln_kernel<<<NROWS, 256>>>(x, gamma, beta);
    gemm_mma_kernel<<<dim3(2, 64, 5), 256, GEMM_SMEM_BYTES>>>(qb, nullptr, 0);
    attn_mma_kernel<<<dim3(8, 8, 8), 256, ATTN_SMEM_BYTES>>>();
    gemm_mma_kernel<<<dim3(2, 64, 1), 256, GEMM_SMEM_BYTES>>>(qb, out, 5);
}